// round 9
// baseline (speedup 1.0000x reference)
#include <cuda_runtime.h>
#include <cuda_fp16.h>
#include <cstdint>

#define HW 16384
#define NB 16
#define AST_H 264      // A smem row stride (halves): 528B/row -> 4-bank shift, conflict-free
#define BSTF  132      // B smem row stride (floats): 528B/row -> 4-bank shift, conflict-free
#define TN    128      // pixels per CTA
#define NTH   512      // threads per CTA (16 warps)
#define NST   4        // B pipeline stages (16 k-rows x 128 px each)
#define A_BYTES (64 * AST_H * 2)      // 33792
#define STG_F   (16 * BSTF)           // floats per B stage (2112)

// Scratch (allocation-free rule: __device__ globals)
__device__ float  g_fc[NB * 4 * 64];       // pooled means [b][k][c]
__device__ __half g_Mh[NB * 64 * 256];     // per-batch fused matrix, fp16

__device__ __forceinline__ void mma_f16(float c[4],
                                        uint32_t a0, uint32_t a1, uint32_t a2, uint32_t a3,
                                        uint32_t b0, uint32_t b1) {
    asm volatile(
        "mma.sync.aligned.m16n8k16.row.col.f32.f16.f16.f32 "
        "{%0,%1,%2,%3},{%4,%5,%6,%7},{%8,%9},{%0,%1,%2,%3};"
        : "+f"(c[0]), "+f"(c[1]), "+f"(c[2]), "+f"(c[3])
        : "r"(a0), "r"(a1), "r"(a2), "r"(a3), "r"(b0), "r"(b1));
}

__device__ __forceinline__ void cp16(uint32_t smem, const void* gmem) {
    asm volatile("cp.async.cg.shared.global [%0], [%1], 16;" :: "r"(smem), "l"(gmem));
}
__device__ __forceinline__ void cp_commit() {
    asm volatile("cp.async.commit_group;");
}

// ncu-steering no-op: keeps the 4-kernel launch period so "-s 5 -c 1" keeps
// landing on k_main.
__global__ void k_nop() {}

// ---------------------------------------------------------------------------
// Kernel 1: adaptive-avg-pool(1). One CTA per (b,k,c) plane. (83% DRAM-bound)
// ---------------------------------------------------------------------------
__global__ void k_pool(const float* __restrict__ low, const float* __restrict__ high,
                       const float* __restrict__ flw, const float* __restrict__ fbk) {
    int plane = blockIdx.x;          // 0..4095
    int b = plane >> 8;
    int k = (plane >> 6) & 3;
    int c = plane & 63;
    const float* src = (k == 0) ? low : (k == 1) ? high : (k == 2) ? flw : fbk;
    src += (size_t)(b * 64 + c) * HW;

    int t = threadIdx.x;
    float s = 0.f;
    const float4* src4 = (const float4*)src;
#pragma unroll
    for (int i = 0; i < 16; i++) {
        float4 v = src4[t + i * 256];
        s += (v.x + v.y) + (v.z + v.w);
    }
    __shared__ float red[8];
#pragma unroll
    for (int off = 16; off; off >>= 1) s += __shfl_down_sync(0xffffffffu, s, off);
    if ((t & 31) == 0) red[t >> 5] = s;
    __syncthreads();
    if (t < 8) {
        s = red[t];
        s += __shfl_down_sync(0xffu, s, 4);
        s += __shfl_down_sync(0xffu, s, 2);
        s += __shfl_down_sync(0xffu, s, 1);
        if (t == 0) g_fc[(b * 4 + k) * 64 + c] = s * (1.0f / HW);
    }
}

// ---------------------------------------------------------------------------
// Kernel 2: adjacency + GCN + SE heads -> fused fp16 matrix M_b. 512 thr/CTA.
// ---------------------------------------------------------------------------
__global__ void __launch_bounds__(512)
k_prep(const float* __restrict__ Wgcn, const float* __restrict__ bgcn,
       const float* __restrict__ W1, const float* __restrict__ b1,
       const float* __restrict__ W2, const float* __restrict__ b2,
       const float* __restrict__ W3, const float* __restrict__ b3,
       const float* __restrict__ W4, const float* __restrict__ b4,
       const float* __restrict__ Wgate) {
    extern __shared__ float sp[];
    float* fc_s  = sp;           // 256
    float* xw_s  = sp + 256;     // 256
    float* h_s   = sp + 512;     // 256
    float* e_s   = sp + 768;     // 256
    float* dot_s = sp + 1024;    // 16
    float* adj_s = sp + 1040;    // 16
    float* wg_s  = sp + 1056;    // 16384 (Wgate copy)

    const int b = blockIdx.x;
    const int t = threadIdx.x;
    const int lane = t & 31;
    const int w = t >> 5;

    // Kick off Wgate staging immediately (64KB, coalesced float4)
    {
        uint32_t swg = (uint32_t)__cvta_generic_to_shared(wg_s);
#pragma unroll
        for (int i = 0; i < 8; i++) {
            int seg = t + i * 512;           // 0..4095
            cp16(swg + (uint32_t)seg * 16, Wgate + seg * 4);
        }
        cp_commit();
    }

    if (t < 256) fc_s[t] = g_fc[b * 256 + t];
    __syncthreads();

    if (t < 16) {                               // pairwise dots [4x4]
        int i = t >> 2, j = t & 3;
        float d = 0.f;
#pragma unroll
        for (int c = 0; c < 64; c++) d += fc_s[i * 64 + c] * fc_s[j * 64 + c];
        dot_s[t] = d;
    }
    __syncthreads();
    if (t < 16) {                               // cosine adjacency
        int i = t >> 2, j = t & 3;
        adj_s[t] = dot_s[t] / (sqrtf(dot_s[i * 4 + i]) * sqrtf(dot_s[j * 4 + j]));
    }
    __syncthreads();
    if (t < 256) {                              // xw = fc @ Wgcn (4x64)
        int j = t >> 6, d = t & 63;
        float a = 0.f;
#pragma unroll 8
        for (int c = 0; c < 64; c++) a += fc_s[j * 64 + c] * Wgcn[c * 64 + d];
        xw_s[t] = a;
    }
    __syncthreads();
    if (t < 256) {                              // h = relu(adj @ xw + bgcn)
        int i = t >> 6, d = t & 63;
        float a = bgcn[d];
#pragma unroll
        for (int j = 0; j < 4; j++) a += adj_s[i * 4 + j] * xw_s[j * 64 + d];
        h_s[t] = fmaxf(a, 0.f);
    }
    __syncthreads();

    // SE heads: warp per 16 outputs; lanes split the 256-dot, shfl-reduce.
    {
#pragma unroll 1
        for (int jj = 0; jj < 16; jj++) {
            int oidx = w * 16 + jj;             // 0..255
            int k = oidx >> 6, j = oidx & 63;
            const float* Wk = (k == 0) ? W1 : (k == 1) ? W2 : (k == 2) ? W3 : W4;
            const float* bk = (k == 0) ? b1 : (k == 1) ? b2 : (k == 2) ? b3 : b4;
            float a = 0.f;
#pragma unroll
            for (int i = 0; i < 8; i++)
                a += h_s[lane + i * 32] * Wk[j * 256 + lane + i * 32];
#pragma unroll
            for (int off = 16; off; off >>= 1) a += __shfl_down_sync(0xffffffffu, a, off);
            if (lane == 0) e_s[oidx] = 1.0f / (1.0f + expf(-(a + bk[j])));
        }
    }
    asm volatile("cp.async.wait_group 0;");     // Wgate staged
    __syncthreads();

    // M_b[o, call] = Gk + e[call] * (Gsum - Gk), all from smem; coalesced fp16 out.
#pragma unroll
    for (int i = 0; i < 32; i++) {
        int idx = t + i * 512;                  // 0..16383
        int o = idx >> 8, call = idx & 255;
        int c = call & 63;
        float gk = wg_s[idx];
        float gsum = wg_s[o * 256 + c] + wg_s[o * 256 + 64 + c] +
                     wg_s[o * 256 + 128 + c] + wg_s[o * 256 + 192 + c];
        float m = gk + e_s[call] * (gsum - gk);
        g_Mh[b * 16384 + idx] = __float2half_rn(m);
    }
}

// ---------------------------------------------------------------------------
// Kernel 3: out = M_b @ X via fp16 mma + bgate.
// CTA = (128-px tile, batch), 512 threads / 16 warps; warp tile m=16 x n=32
// (acc 16 regs -> <=42 regs, 3 CTAs/SM = 75% occupancy).
// B: 4-stage cp.async ring of FLOAT stages (16 k-rows x 128 px).
// ---------------------------------------------------------------------------
__global__ void __launch_bounds__(NTH, 3)
k_main(const float* __restrict__ low, const float* __restrict__ high,
       const float* __restrict__ flw, const float* __restrict__ fbk,
       const float* __restrict__ bgate, float* __restrict__ out) {
    extern __shared__ char smc[];
    __half* A_h = (__half*)smc;                    // [64][AST_H] halves
    float*  B_f = (float*)(smc + A_BYTES);         // NST x [16][BSTF] floats

    const int b   = blockIdx.y;
    const int px0 = blockIdx.x * TN;
    const int t    = threadIdx.x;
    const int lane = t & 31;
    const int w    = t >> 5;
    const int r2 = lane >> 2;   // 0..7
    const int r4 = lane & 3;    // 0..3
    const int wm = w >> 2;      // 0..3  (m quarter, 16 rows)
    const int wn = w & 3;       // 0..3  (n quarter, 32 px)

    const uint32_t sA = (uint32_t)__cvta_generic_to_shared(A_h);
    const uint32_t sB = (uint32_t)__cvta_generic_to_shared(B_f);
    const float* xp[4] = {low, high, flw, fbk};

    // Per-thread staging coords: 512 16B-segments per stage, 1 per thread.
    const int row0 = t >> 5;           // k-row 0..15
    const int seg0 = t & 31;           // 16B segment 0..31

    auto issue_stage = [&](int s) {
        const float* base = xp[s >> 2] + (size_t)(b * 64 + (s & 3) * 16) * HW + px0;
        uint32_t dst = sB + (uint32_t)((s & (NST - 1)) * STG_F) * 4;
        cp16(dst + (uint32_t)(row0 * BSTF + seg0 * 4) * 4,
             base + (size_t)row0 * HW + seg0 * 4);
    };

    // Prologue: group0 = A + stage0; groups 1..2 = stages 1..2.
    {
        const __half* Mg = g_Mh + b * 16384;
#pragma unroll
        for (int i = 0; i < 4; i++) {
            int idx = t + i * NTH;             // 0..2047
            int o = idx >> 5, seg = idx & 31;
            cp16(sA + (uint32_t)(o * AST_H + seg * 8) * 2, Mg + o * 256 + seg * 8);
        }
        issue_stage(0); cp_commit();
        issue_stage(1); cp_commit();
        issue_stage(2); cp_commit();
    }

    float acc[4][4];
#pragma unroll
    for (int nf = 0; nf < 4; nf++)
#pragma unroll
        for (int q = 0; q < 4; q++) acc[nf][q] = 0.f;

#pragma unroll 1
    for (int s = 0; s < 16; s++) {
        asm volatile("cp.async.wait_group 2;");   // stage s landed
        __syncthreads();
        if (s + 3 < 16) issue_stage(s + 3);       // refill buffer (s+3)%4 == (s-1)%4
        cp_commit();                              // always: uniform ledger

        const float* Bb = B_f + (s & (NST - 1)) * STG_F;
        const __half* ap = A_h + (wm * 16 + r2) * AST_H + s * 16 + 2 * r4;
        uint32_t a0[4];
        a0[0] = *(const uint32_t*)(ap);
        a0[1] = *(const uint32_t*)(ap + 8 * AST_H);
        a0[2] = *(const uint32_t*)(ap + 8);
        a0[3] = *(const uint32_t*)(ap + 8 * AST_H + 8);

        const float* bp = Bb + 2 * r4 * BSTF + wn * 32 + r2;
#pragma unroll
        for (int nf = 0; nf < 4; nf++) {
            const float* q = bp + nf * 8;
            __half2 h0 = __floats2half2_rn(q[0], q[BSTF]);
            __half2 h1 = __floats2half2_rn(q[8 * BSTF], q[9 * BSTF]);
            uint32_t b0 = *(uint32_t*)&h0;
            uint32_t b1 = *(uint32_t*)&h1;
            mma_f16(acc[nf], a0[0], a0[1], a0[2], a0[3], b0, b1);
        }
    }

    // Epilogue: + bgate, float2 stores (full 32B sectors)
    {
        int o_lo = wm * 16 + r2;
        int o_hi = o_lo + 8;
        float bgl = __ldg(bgate + o_lo);
        float bgh = __ldg(bgate + o_hi);
        float* olo = out + (size_t)(b * 64 + o_lo) * HW + px0 + wn * 32 + 2 * r4;
        float* ohi = out + (size_t)(b * 64 + o_hi) * HW + px0 + wn * 32 + 2 * r4;
#pragma unroll
        for (int nf = 0; nf < 4; nf++) {
            float2 v0 = {acc[nf][0] + bgl, acc[nf][1] + bgl};
            float2 v1 = {acc[nf][2] + bgh, acc[nf][3] + bgh};
            *(float2*)(olo + nf * 8) = v0;
            *(float2*)(ohi + nf * 8) = v1;
        }
    }
}

// ---------------------------------------------------------------------------
extern "C" void kernel_launch(void* const* d_in, const int* in_sizes, int n_in,
                              void* d_out, int out_size) {
    const float* low   = (const float*)d_in[0];
    const float* high  = (const float*)d_in[1];
    const float* flw   = (const float*)d_in[2];
    const float* fbk   = (const float*)d_in[3];
    const float* Wgcn  = (const float*)d_in[4];
    const float* bgcn  = (const float*)d_in[5];
    const float* W1    = (const float*)d_in[6];
    const float* b1    = (const float*)d_in[7];
    const float* W2    = (const float*)d_in[8];
    const float* b2    = (const float*)d_in[9];
    const float* W3    = (const float*)d_in[10];
    const float* b3    = (const float*)d_in[11];
    const float* W4    = (const float*)d_in[12];
    const float* b4    = (const float*)d_in[13];
    const float* Wgate = (const float*)d_in[14];
    const float* bgate = (const float*)d_in[15];
    float* out = (float*)d_out;

    k_pool<<<4096, 256>>>(low, high, flw, fbk);

    const int smem_p = (1056 + 16384) * (int)sizeof(float);  // 69,760 B
    cudaFuncSetAttribute(k_prep, cudaFuncAttributeMaxDynamicSharedMemorySize, smem_p);
    k_prep<<<16, 512, smem_p>>>(Wgcn, bgcn, W1, b1, W2, b2, W3, b3, W4, b4, Wgate);

    k_nop<<<1, 32>>>();   // keeps ncu -s 5 landing on k_main

    const int smem = A_BYTES + NST * STG_F * (int)sizeof(float);  // 67,584 B
    cudaFuncSetAttribute(k_main, cudaFuncAttributeMaxDynamicSharedMemorySize, smem);
    k_main<<<dim3(HW / TN, NB), NTH, smem>>>(low, high, flw, fbk, bgate, out);
}

// round 10
// speedup vs baseline: 1.1359x; 1.1359x over previous
#include <cuda_runtime.h>
#include <cuda_fp16.h>
#include <cstdint>

#define HW 16384
#define NB 16
#define AST_H 264      // A smem row stride (halves): 528B/row -> 4-bank shift, conflict-free
#define BSTF  260      // B smem row stride (floats): 1040B/row -> 4-bank shift, conflict-free
#define TN    256      // pixels per CTA
#define NTH   512      // threads per CTA (16 warps)
#define NST   4        // B pipeline stages (16 k-rows x 256 px each)
#define A_BYTES (64 * AST_H * 2)      // 33792
#define STG_F   (16 * BSTF)           // floats per B stage (4160)

// Scratch (allocation-free rule: __device__ globals)
__device__ float  g_fc[NB * 4 * 64];       // pooled means [b][k][c]
__device__ __half g_Mh[NB * 64 * 256];     // per-batch fused matrix, fp16

__device__ __forceinline__ void mma_f16(float c[4],
                                        uint32_t a0, uint32_t a1, uint32_t a2, uint32_t a3,
                                        uint32_t b0, uint32_t b1) {
    asm volatile(
        "mma.sync.aligned.m16n8k16.row.col.f32.f16.f16.f32 "
        "{%0,%1,%2,%3},{%4,%5,%6,%7},{%8,%9},{%0,%1,%2,%3};"
        : "+f"(c[0]), "+f"(c[1]), "+f"(c[2]), "+f"(c[3])
        : "r"(a0), "r"(a1), "r"(a2), "r"(a3), "r"(b0), "r"(b1));
}

__device__ __forceinline__ void cp16(uint32_t smem, const void* gmem) {
    asm volatile("cp.async.cg.shared.global [%0], [%1], 16;" :: "r"(smem), "l"(gmem));
}
__device__ __forceinline__ void cp_commit() {
    asm volatile("cp.async.commit_group;");
}

// ncu-steering no-op: keeps the 4-kernel launch period so "-s 5 -c 1" keeps
// landing on k_main.
__global__ void k_nop() {}

// ---------------------------------------------------------------------------
// Kernel 1: adaptive-avg-pool(1). One CTA per (b,k,c) plane. (83% DRAM-bound)
// ---------------------------------------------------------------------------
__global__ void k_pool(const float* __restrict__ low, const float* __restrict__ high,
                       const float* __restrict__ flw, const float* __restrict__ fbk) {
    int plane = blockIdx.x;          // 0..4095
    int b = plane >> 8;
    int k = (plane >> 6) & 3;
    int c = plane & 63;
    const float* src = (k == 0) ? low : (k == 1) ? high : (k == 2) ? flw : fbk;
    src += (size_t)(b * 64 + c) * HW;

    int t = threadIdx.x;
    float s = 0.f;
    const float4* src4 = (const float4*)src;
#pragma unroll
    for (int i = 0; i < 16; i++) {
        float4 v = src4[t + i * 256];
        s += (v.x + v.y) + (v.z + v.w);
    }
    __shared__ float red[8];
#pragma unroll
    for (int off = 16; off; off >>= 1) s += __shfl_down_sync(0xffffffffu, s, off);
    if ((t & 31) == 0) red[t >> 5] = s;
    __syncthreads();
    if (t < 8) {
        s = red[t];
        s += __shfl_down_sync(0xffu, s, 4);
        s += __shfl_down_sync(0xffu, s, 2);
        s += __shfl_down_sync(0xffu, s, 1);
        if (t == 0) g_fc[(b * 4 + k) * 64 + c] = s * (1.0f / HW);
    }
}

// ---------------------------------------------------------------------------
// Kernel 2 (SPLIT to 64 CTAs): grid (16 batches x 4 row-quarters).
// Each CTA: tiny GCN/SE phases (duplicated, ~0 cost) + stages its own 16KB
// Wgate slice + builds 16 rows of M_b. 4x parallelism vs R8.
// ---------------------------------------------------------------------------
__global__ void __launch_bounds__(512)
k_prep(const float* __restrict__ Wgcn, const float* __restrict__ bgcn,
       const float* __restrict__ W1, const float* __restrict__ b1,
       const float* __restrict__ W2, const float* __restrict__ b2,
       const float* __restrict__ W3, const float* __restrict__ b3,
       const float* __restrict__ W4, const float* __restrict__ b4,
       const float* __restrict__ Wgate) {
    extern __shared__ float sp[];
    float* fc_s  = sp;           // 256
    float* xw_s  = sp + 256;     // 256
    float* h_s   = sp + 512;     // 256
    float* e_s   = sp + 768;     // 256
    float* dot_s = sp + 1024;    // 16
    float* adj_s = sp + 1040;    // 16
    float* wg_s  = sp + 1056;    // 4096 (16-row Wgate slice)

    const int b  = blockIdx.x;
    const int o0 = blockIdx.y * 16;      // this CTA's output-row base
    const int t  = threadIdx.x;
    const int lane = t & 31;
    const int w = t >> 5;

    // Kick off staging of this CTA's Wgate slice (16 rows x 256 = 16KB)
    {
        uint32_t swg = (uint32_t)__cvta_generic_to_shared(wg_s);
#pragma unroll
        for (int i = 0; i < 2; i++) {
            int seg = t + i * 512;           // 0..1023 (16B segments)
            cp16(swg + (uint32_t)seg * 16, Wgate + o0 * 256 + seg * 4);
        }
        cp_commit();
    }

    if (t < 256) fc_s[t] = g_fc[b * 256 + t];
    __syncthreads();

    if (t < 16) {                               // pairwise dots [4x4]
        int i = t >> 2, j = t & 3;
        float d = 0.f;
#pragma unroll
        for (int c = 0; c < 64; c++) d += fc_s[i * 64 + c] * fc_s[j * 64 + c];
        dot_s[t] = d;
    }
    __syncthreads();
    if (t < 16) {                               // cosine adjacency
        int i = t >> 2, j = t & 3;
        adj_s[t] = dot_s[t] / (sqrtf(dot_s[i * 4 + i]) * sqrtf(dot_s[j * 4 + j]));
    }
    __syncthreads();
    if (t < 256) {                              // xw = fc @ Wgcn (4x64)
        int j = t >> 6, d = t & 63;
        float a = 0.f;
#pragma unroll 8
        for (int c = 0; c < 64; c++) a += fc_s[j * 64 + c] * Wgcn[c * 64 + d];
        xw_s[t] = a;
    }
    __syncthreads();
    if (t < 256) {                              // h = relu(adj @ xw + bgcn)
        int i = t >> 6, d = t & 63;
        float a = bgcn[d];
#pragma unroll
        for (int j = 0; j < 4; j++) a += adj_s[i * 4 + j] * xw_s[j * 64 + d];
        h_s[t] = fmaxf(a, 0.f);
    }
    __syncthreads();

    // SE heads: warp per 16 outputs; lanes split the 256-dot, shfl-reduce.
    {
#pragma unroll 1
        for (int jj = 0; jj < 16; jj++) {
            int oidx = w * 16 + jj;             // 0..255
            int k = oidx >> 6, j = oidx & 63;
            const float* Wk = (k == 0) ? W1 : (k == 1) ? W2 : (k == 2) ? W3 : W4;
            const float* bk = (k == 0) ? b1 : (k == 1) ? b2 : (k == 2) ? b3 : b4;
            float a = 0.f;
#pragma unroll
            for (int i = 0; i < 8; i++)
                a += h_s[lane + i * 32] * Wk[j * 256 + lane + i * 32];
#pragma unroll
            for (int off = 16; off; off >>= 1) a += __shfl_down_sync(0xffffffffu, a, off);
            if (lane == 0) e_s[oidx] = 1.0f / (1.0f + expf(-(a + bk[j])));
        }
    }
    asm volatile("cp.async.wait_group 0;");     // Wgate slice staged
    __syncthreads();

    // M_b rows [o0, o0+16): Gk + e[call] * (Gsum - Gk); coalesced fp16 out.
#pragma unroll
    for (int i = 0; i < 8; i++) {
        int idx = t + i * 512;                  // 0..4095
        int o_l = idx >> 8, call = idx & 255;
        int c = call & 63;
        float gk = wg_s[idx];
        float gsum = wg_s[o_l * 256 + c] + wg_s[o_l * 256 + 64 + c] +
                     wg_s[o_l * 256 + 128 + c] + wg_s[o_l * 256 + 192 + c];
        float m = gk + e_s[call] * (gsum - gk);
        g_Mh[b * 16384 + (o0 + o_l) * 256 + call] = __float2half_rn(m);
    }
}

// ---------------------------------------------------------------------------
// Kernel 3 (EXACT R8 config — known 71.5us): out = M_b @ X via fp16 mma.
// CTA = (256-px tile, batch), 512 threads / 16 warps; warp tile m=32 x n=32.
// B: 4-stage cp.async ring of FLOAT stages (16 k-rows x 256 px).
// ---------------------------------------------------------------------------
__global__ void __launch_bounds__(NTH, 2)
k_main(const float* __restrict__ low, const float* __restrict__ high,
       const float* __restrict__ flw, const float* __restrict__ fbk,
       const float* __restrict__ bgate, float* __restrict__ out) {
    extern __shared__ char smc[];
    __half* A_h = (__half*)smc;                    // [64][AST_H] halves
    float*  B_f = (float*)(smc + A_BYTES);         // NST x [16][BSTF] floats

    const int b   = blockIdx.y;
    const int px0 = blockIdx.x * TN;
    const int t    = threadIdx.x;
    const int lane = t & 31;
    const int w    = t >> 5;
    const int r2 = lane >> 2;   // 0..7
    const int r4 = lane & 3;    // 0..3
    const int wm = w >> 3;      // 0..1  (m half)
    const int wn = w & 7;       // 0..7  (n eighth, 32 px each)

    const uint32_t sA = (uint32_t)__cvta_generic_to_shared(A_h);
    const uint32_t sB = (uint32_t)__cvta_generic_to_shared(B_f);
    const float* xp[4] = {low, high, flw, fbk};

    const int row0 = t >> 5;           // k-row 0..15
    const int seg0 = t & 31;           // 16B segment; +32 for i=1

    auto issue_stage = [&](int s) {
        const float* base = xp[s >> 2] + (size_t)(b * 64 + (s & 3) * 16) * HW + px0;
        uint32_t dst = sB + (uint32_t)((s & (NST - 1)) * STG_F) * 4;
#pragma unroll
        for (int i = 0; i < 2; i++) {
            int seg = seg0 + i * 32;   // 0..63
            cp16(dst + (uint32_t)(row0 * BSTF + seg * 4) * 4,
                 base + (size_t)row0 * HW + seg * 4);
        }
    };

    // Prologue: group0 = A + stage0; groups 1..2 = stages 1..2.
    {
        const __half* Mg = g_Mh + b * 16384;
#pragma unroll
        for (int i = 0; i < 4; i++) {
            int idx = t + i * NTH;             // 0..2047
            int o = idx >> 5, seg = idx & 31;
            cp16(sA + (uint32_t)(o * AST_H + seg * 8) * 2, Mg + o * 256 + seg * 8);
        }
        issue_stage(0); cp_commit();
        issue_stage(1); cp_commit();
        issue_stage(2); cp_commit();
    }

    float acc[2][4][4];
#pragma unroll
    for (int mt = 0; mt < 2; mt++)
#pragma unroll
        for (int nf = 0; nf < 4; nf++)
#pragma unroll
            for (int q = 0; q < 4; q++) acc[mt][nf][q] = 0.f;

#pragma unroll 1
    for (int s = 0; s < 16; s++) {
        asm volatile("cp.async.wait_group 2;");   // stage s landed
        __syncthreads();
        if (s + 3 < 16) issue_stage(s + 3);       // refill buffer (s+3)%4 == (s-1)%4
        cp_commit();                              // always: uniform ledger

        const float* Bb = B_f + (s & (NST - 1)) * STG_F;
        const __half* ap = A_h + (wm * 32 + r2) * AST_H + s * 16 + 2 * r4;
        uint32_t a0[4], a1[4];
        a0[0] = *(const uint32_t*)(ap);
        a0[1] = *(const uint32_t*)(ap + 8 * AST_H);
        a0[2] = *(const uint32_t*)(ap + 8);
        a0[3] = *(const uint32_t*)(ap + 8 * AST_H + 8);
        a1[0] = *(const uint32_t*)(ap + 16 * AST_H);
        a1[1] = *(const uint32_t*)(ap + 24 * AST_H);
        a1[2] = *(const uint32_t*)(ap + 16 * AST_H + 8);
        a1[3] = *(const uint32_t*)(ap + 24 * AST_H + 8);

        const float* bp = Bb + 2 * r4 * BSTF + wn * 32 + r2;
#pragma unroll
        for (int nf = 0; nf < 4; nf++) {
            const float* q = bp + nf * 8;
            __half2 h0 = __floats2half2_rn(q[0], q[BSTF]);
            __half2 h1 = __floats2half2_rn(q[8 * BSTF], q[9 * BSTF]);
            uint32_t b0 = *(uint32_t*)&h0;
            uint32_t b1 = *(uint32_t*)&h1;
            mma_f16(acc[0][nf], a0[0], a0[1], a0[2], a0[3], b0, b1);
            mma_f16(acc[1][nf], a1[0], a1[1], a1[2], a1[3], b0, b1);
        }
    }

    // Epilogue: + bgate, float2 stores (full 32B sectors)
#pragma unroll
    for (int mt = 0; mt < 2; mt++) {
        int o_lo = wm * 32 + mt * 16 + r2;
        int o_hi = o_lo + 8;
        float bgl = __ldg(bgate + o_lo);
        float bgh = __ldg(bgate + o_hi);
        float* olo = out + (size_t)(b * 64 + o_lo) * HW + px0 + wn * 32 + 2 * r4;
        float* ohi = out + (size_t)(b * 64 + o_hi) * HW + px0 + wn * 32 + 2 * r4;
#pragma unroll
        for (int nf = 0; nf < 4; nf++) {
            float2 v0 = {acc[mt][nf][0] + bgl, acc[mt][nf][1] + bgl};
            float2 v1 = {acc[mt][nf][2] + bgh, acc[mt][nf][3] + bgh};
            *(float2*)(olo + nf * 8) = v0;
            *(float2*)(ohi + nf * 8) = v1;
        }
    }
}

// ---------------------------------------------------------------------------
extern "C" void kernel_launch(void* const* d_in, const int* in_sizes, int n_in,
                              void* d_out, int out_size) {
    const float* low   = (const float*)d_in[0];
    const float* high  = (const float*)d_in[1];
    const float* flw   = (const float*)d_in[2];
    const float* fbk   = (const float*)d_in[3];
    const float* Wgcn  = (const float*)d_in[4];
    const float* bgcn  = (const float*)d_in[5];
    const float* W1    = (const float*)d_in[6];
    const float* b1    = (const float*)d_in[7];
    const float* W2    = (const float*)d_in[8];
    const float* b2    = (const float*)d_in[9];
    const float* W3    = (const float*)d_in[10];
    const float* b3    = (const float*)d_in[11];
    const float* W4    = (const float*)d_in[12];
    const float* b4    = (const float*)d_in[13];
    const float* Wgate = (const float*)d_in[14];
    const float* bgate = (const float*)d_in[15];
    float* out = (float*)d_out;

    k_pool<<<4096, 256>>>(low, high, flw, fbk);

    const int smem_p = (1056 + 4096) * (int)sizeof(float);  // 20,608 B
    cudaFuncSetAttribute(k_prep, cudaFuncAttributeMaxDynamicSharedMemorySize, smem_p);
    k_prep<<<dim3(16, 4), 512, smem_p>>>(Wgcn, bgcn, W1, b1, W2, b2, W3, b3, W4, b4, Wgate);

    k_nop<<<1, 32>>>();   // keeps ncu -s 5 landing on k_main

    const int smem = A_BYTES + NST * STG_F * (int)sizeof(float);  // 100,352 B
    cudaFuncSetAttribute(k_main, cudaFuncAttributeMaxDynamicSharedMemorySize, smem);
    k_main<<<dim3(HW / TN, NB), NTH, smem>>>(low, high, flw, fbk, bgate, out);
}